// round 17
// baseline (speedup 1.0000x reference)
#include <cuda_runtime.h>
#include <cuda_fp16.h>

// Problem dims (fixed by dataset): N=30000, F=16, S=8, H=16, E=300000
#define NMAX 30080
#define PRE_BLOCKS 148

// g, line-split j-major layout (256 B per node row):
//   bytes [  0..127]: chunks c0 = slices t0..3 for j=0..7, 16 B each at j*16
//   bytes [128..255]: chunks c1 = slices t4..7 for j=0..7, 16 B each
// -> each edge-gather LDG.128 touches exactly ONE 128B line per row.
__device__ __half   g8[(size_t)NMAX * 128];
__device__ unsigned gbias[(size_t)NMAX * 8];
__device__ float    agg_buf[(size_t)NMAX * 16];
__device__ unsigned pooled_bits[16];   // raw float bits of max(relu(agg)) >= 0

__device__ __forceinline__ void mma16816(float d[4],
    unsigned a0, unsigned a1, unsigned a2, unsigned a3,
    unsigned b0, unsigned b1)
{
    float z = 0.0f;
    asm("mma.sync.aligned.m16n8k16.row.col.f32.f16.f16.f32 "
        "{%0,%1,%2,%3}, {%4,%5,%6,%7}, {%8,%9}, {%10,%11,%12,%13};"
        : "=f"(d[0]), "=f"(d[1]), "=f"(d[2]), "=f"(d[3])
        : "r"(a0), "r"(a1), "r"(a2), "r"(a3), "r"(b0), "r"(b1),
          "f"(z), "f"(z), "f"(z), "f"(z));
}

__device__ __forceinline__ unsigned f2h2(float lo, float hi)
{
    __half2 h = __floats2half2_rn(lo, hi);
    return *(unsigned*)&h;
}

// ---------------------------------------------------------------------------
// Kernel P (HMMA): g[N x 160] = x[N x 16] @ Wtilde[16 x 160], fp16 in/fp32 acc.
// 148 blocks x 16 warps; warp (b,w) handles slab b + 148w -> <= 1 slab each.
// ---------------------------------------------------------------------------
struct AFrag { unsigned a0, a1, a2, a3; int na, nb; };

__device__ __forceinline__ AFrag load_afrag(const float2* X2, int n0, int r,
                                            int m, int N)
{
    AFrag f;
    f.na = n0 + r; f.nb = n0 + r + 8;
    int nac = (f.na < N) ? f.na : N - 1;
    int nbc = (f.nb < N) ? f.nb : N - 1;
    float2 xa0 = __ldg(X2 + (size_t)nac * 8 + m);
    float2 xa2 = __ldg(X2 + (size_t)nac * 8 + m + 4);
    float2 xa1 = __ldg(X2 + (size_t)nbc * 8 + m);
    float2 xa3 = __ldg(X2 + (size_t)nbc * 8 + m + 4);
    f.a0 = f2h2(xa0.x, xa0.y);
    f.a1 = f2h2(xa1.x, xa1.y);
    f.a2 = f2h2(xa2.x, xa2.y);
    f.a3 = f2h2(xa3.x, xa3.y);
    return f;
}

__global__ void __launch_bounds__(512) node_pre(const float* __restrict__ x,
                                                const float* __restrict__ Wk,
                                                const float* __restrict__ bk,
                                                const float* __restrict__ Wr,
                                                const float* __restrict__ br,
                                                int N)
{
    __shared__ __half Whs[160 * 18];                 // [c][f], stride 18 (pad)

    int tid = threadIdx.x;
    int w = tid >> 5;
    int l = tid & 31;
    int r = l >> 2;
    int m = l & 3;

    int nslabs = (N + 15) >> 4;
    const float2* X2 = (const float2*)x;

    int slab0 = blockIdx.x + PRE_BLOCKS * w;
    AFrag af;
    if (slab0 < nslabs) af = load_afrag(X2, slab0 * 16, r, m, N);

    for (int i = tid; i < 2560; i += 512) {
        int c = i >> 4, f = i & 15;
        int t = c >> 4, h = c & 15;
        float v = (t < 8) ? Wk[t * 256 + f * 16 + h]
                : (t == 8) ? bk[f * 16 + h] : Wr[f * 16 + h];
        Whs[c * 18 + f] = __float2half_rn(v);
    }
    __syncthreads();

    float br0 = br[2 * m], br1 = br[2 * m + 1];
    float br8 = br[8 + 2 * m], br9 = br[9 + 2 * m];

    for (int slab = slab0; slab < nslabs; slab += PRE_BLOCKS * 16) {
        if (slab != slab0) af = load_afrag(X2, slab * 16, r, m, N);
        int na = af.na, nb = af.nb;

        unsigned outA[2][8], outB[2][8];

#pragma unroll
        for (int nt = 0; nt < 20; nt++) {
            int c = nt * 8 + r;
            unsigned b0 = *(const unsigned*)&Whs[c * 18 + 2 * m];
            unsigned b1 = *(const unsigned*)&Whs[c * 18 + 2 * m + 8];
            float d[4];
            mma16816(d, af.a0, af.a1, af.a2, af.a3, b0, b1);
            int jh = nt & 1;
            int j  = m + 4 * jh;
            if (nt < 16) {
                int t = nt >> 1;
                outA[jh][t] = f2h2(d[0], d[1]);
                outB[jh][t] = f2h2(d[2], d[3]);
            } else if (nt < 18) {
                if (na < N) gbias[na * 8 + j] = f2h2(d[0], d[1]);
                if (nb < N) gbias[nb * 8 + j] = f2h2(d[2], d[3]);
            } else {
                float c0 = jh ? br8 : br0;
                float c1 = jh ? br9 : br1;
                if (na < N)
                    *(float2*)(agg_buf + (size_t)na * 16 + 2 * j) =
                        make_float2(d[0] + c0, d[1] + c1);
                if (nb < N)
                    *(float2*)(agg_buf + (size_t)nb * 16 + 2 * j) =
                        make_float2(d[2] + c0, d[3] + c1);
            }
        }

        // Line-split stores: c0 chunk -> line 0 at j*16B, c1 -> line 1.
#pragma unroll
        for (int jh = 0; jh < 2; jh++) {
            int j = m + 4 * jh;
            if (na < N) {
                uint4* p = (uint4*)(g8 + (size_t)na * 128 + j * 8);
                p[0] = make_uint4(outA[jh][0], outA[jh][1], outA[jh][2], outA[jh][3]);
                p[8] = make_uint4(outA[jh][4], outA[jh][5], outA[jh][6], outA[jh][7]);
            }
            if (nb < N) {
                uint4* p = (uint4*)(g8 + (size_t)nb * 128 + j * 8);
                p[0] = make_uint4(outB[jh][0], outB[jh][1], outB[jh][2], outB[jh][3]);
                p[8] = make_uint4(outB[jh][4], outB[jh][5], outB[jh][6], outB[jh][7]);
            }
        }
    }
}

// ---------------------------------------------------------------------------
// Kernel E: per-edge gather + dot + red.v2 scatter. Line-split g layout.
// e/src/dst via __ldcs (read-once, evict-first). PDL: independent loads
// hoisted above cudaGridDependencySynchronize().
// ---------------------------------------------------------------------------
__global__ void __launch_bounds__(256) edge_kernel(const float* __restrict__ e,
                                                   const int* __restrict__ src,
                                                   const int* __restrict__ dst,
                                                   int E)
{
    if (blockIdx.x == 0 && threadIdx.x < 16)
        pooled_bits[threadIdx.x] = 0u;   // = 0.0f

    int t = blockIdx.x * 256 + threadIdx.x;
    int gid = t >> 3;
    bool act = (gid < E);
    int j = t & 7;

    int sn = 0, dn = 0;
    float4 e0 = make_float4(0.f, 0.f, 0.f, 0.f), e1 = e0;
    if (act) {
        sn = __ldcs(src + gid);
        dn = __ldcs(dst + gid);
        const float4* ep = (const float4*)e + (size_t)gid * 2;
        e0 = __ldcs(ep);
        e1 = __ldcs(ep + 1);
    }

    cudaGridDependencySynchronize();
    if (!act) return;

    const uint4* gp = (const uint4*)(g8 + (size_t)sn * 128 + j * 8);
    uint4 a = __ldg(gp);          // line 0: slices t0..3
    uint4 b = __ldg(gp + 8);      // line 1: slices t4..7
    unsigned gb = __ldg(gbias + sn * 8 + j);

    float2 w0 = __half22float2(*(__half2*)&a.x);
    float2 w1 = __half22float2(*(__half2*)&a.y);
    float2 w2 = __half22float2(*(__half2*)&a.z);
    float2 w3 = __half22float2(*(__half2*)&a.w);
    float2 w4 = __half22float2(*(__half2*)&b.x);
    float2 w5 = __half22float2(*(__half2*)&b.y);
    float2 w6 = __half22float2(*(__half2*)&b.z);
    float2 w7 = __half22float2(*(__half2*)&b.w);
    float2 wb = __half22float2(*(__half2*)&gb);

    float ax = wb.x, ay = wb.y;
    ax = fmaf(e0.x, w0.x, ax);  ay = fmaf(e0.x, w0.y, ay);
    ax = fmaf(e0.y, w1.x, ax);  ay = fmaf(e0.y, w1.y, ay);
    ax = fmaf(e0.z, w2.x, ax);  ay = fmaf(e0.z, w2.y, ay);
    ax = fmaf(e0.w, w3.x, ax);  ay = fmaf(e0.w, w3.y, ay);
    ax = fmaf(e1.x, w4.x, ax);  ay = fmaf(e1.x, w4.y, ay);
    ax = fmaf(e1.y, w5.x, ax);  ay = fmaf(e1.y, w5.y, ay);
    ax = fmaf(e1.z, w6.x, ax);  ay = fmaf(e1.z, w6.y, ay);
    ax = fmaf(e1.w, w7.x, ax);  ay = fmaf(e1.w, w7.y, ay);

    float* o = agg_buf + (size_t)dn * 16 + 2 * j;
    asm volatile("red.global.add.v2.f32 [%0], {%1, %2};"
                 :: "l"(o), "f"(ax), "f"(ay) : "memory");
}

// ---------------------------------------------------------------------------
// Kernel C: relu + max-pool only (BN deferred; finalize is its own kernel).
// Vector-halving warp reduction (31 shfl); unsigned atomicMax on raw bits.
// ---------------------------------------------------------------------------
__global__ void __launch_bounds__(256) node_post(int N)
{
    __shared__ float wmax[8][16];
    int n = blockIdx.x * 256 + threadIdx.x;
    int l = threadIdx.x & 31;

    cudaGridDependencySynchronize();   // wait for all edge reds

    float v[16];
    if (n < N) {
        const float4* ar = (const float4*)(agg_buf + (size_t)n * 16);
#pragma unroll
        for (int q = 0; q < 4; q++) {
            float4 a = __ldcg(ar + q);
            v[4 * q + 0] = fmaxf(a.x, 0.0f); v[4 * q + 1] = fmaxf(a.y, 0.0f);
            v[4 * q + 2] = fmaxf(a.z, 0.0f); v[4 * q + 3] = fmaxf(a.w, 0.0f);
        }
    } else {
#pragma unroll
        for (int h = 0; h < 16; h++) v[h] = 0.0f;
    }

    {
        float r[16];
#pragma unroll
        for (int i = 0; i < 16; i++) r[i] = __shfl_xor_sync(0xffffffffu, v[i], 16);
        if (l & 16) {
#pragma unroll
            for (int i = 0; i < 8; i++) v[i] = fmaxf(v[i + 8], r[i + 8]);
        } else {
#pragma unroll
            for (int i = 0; i < 8; i++) v[i] = fmaxf(v[i], r[i]);
        }
    }
    {
        float r[8];
#pragma unroll
        for (int i = 0; i < 8; i++) r[i] = __shfl_xor_sync(0xffffffffu, v[i], 8);
        if (l & 8) {
#pragma unroll
            for (int i = 0; i < 4; i++) v[i] = fmaxf(v[i + 4], r[i + 4]);
        } else {
#pragma unroll
            for (int i = 0; i < 4; i++) v[i] = fmaxf(v[i], r[i]);
        }
    }
    {
        float r[4];
#pragma unroll
        for (int i = 0; i < 4; i++) r[i] = __shfl_xor_sync(0xffffffffu, v[i], 4);
        if (l & 4) {
            v[0] = fmaxf(v[2], r[2]); v[1] = fmaxf(v[3], r[3]);
        } else {
            v[0] = fmaxf(v[0], r[0]); v[1] = fmaxf(v[1], r[1]);
        }
    }
    {
        float r0 = __shfl_xor_sync(0xffffffffu, v[0], 2);
        float r1 = __shfl_xor_sync(0xffffffffu, v[1], 2);
        v[0] = (l & 2) ? fmaxf(v[1], r1) : fmaxf(v[0], r0);
    }
    v[0] = fmaxf(v[0], __shfl_xor_sync(0xffffffffu, v[0], 1));

    int wid = threadIdx.x >> 5;
    if ((l & 1) == 0) wmax[wid][(l >> 1) & 15] = v[0];
    __syncthreads();

    if (threadIdx.x < 16) {
        float m = wmax[0][threadIdx.x];
#pragma unroll
        for (int w2 = 1; w2 < 8; w2++) m = fmaxf(m, wmax[w2][threadIdx.x]);
        atomicMax(&pooled_bits[threadIdx.x], __float_as_uint(m));
    }
}

// ---------------------------------------------------------------------------
// Kernel F: finalize (PDL, 1 block): BN on the 16 pooled maxes + 16x3 dense.
// ---------------------------------------------------------------------------
__global__ void finalize(const float* __restrict__ gamma,
                         const float* __restrict__ beta,
                         const float* __restrict__ mmean,
                         const float* __restrict__ mvar,
                         const float* __restrict__ Wd,
                         const float* __restrict__ bd,
                         float* __restrict__ out)
{
    __shared__ float pooled[16];
    int t = threadIdx.x;

    cudaGridDependencySynchronize();   // wait for node_post grid

    if (t < 16) {
        float raw = __uint_as_float(pooled_bits[t]);
        float sc = gamma[t] * rsqrtf(mvar[t] + 1e-3f);
        pooled[t] = raw * sc + (beta[t] - mmean[t] * sc);
    }
    __syncwarp();
    if (t < 3) {
        float s = bd[t];
#pragma unroll
        for (int h = 0; h < 16; h++) s += pooled[h] * Wd[h * 3 + t];
        out[t] = s;
    }
}

// ---------------------------------------------------------------------------
extern "C" void kernel_launch(void* const* d_in, const int* in_sizes, int n_in,
                              void* d_out, int out_size)
{
    const float* x     = (const float*)d_in[0];
    const float* e     = (const float*)d_in[1];
    const int*   src   = (const int*)d_in[2];
    const int*   dst   = (const int*)d_in[3];
    const float* Wk    = (const float*)d_in[4];
    const float* bk    = (const float*)d_in[5];
    const float* Wr    = (const float*)d_in[6];
    const float* br    = (const float*)d_in[7];
    const float* gamma = (const float*)d_in[8];
    const float* beta  = (const float*)d_in[9];
    const float* mmean = (const float*)d_in[10];
    const float* mvar  = (const float*)d_in[11];
    const float* Wd    = (const float*)d_in[12];
    const float* bd    = (const float*)d_in[13];

    int N = in_sizes[0] / 16;   // F = 16
    int E = in_sizes[2];

    node_pre<<<PRE_BLOCKS, 512>>>(x, Wk, bk, Wr, br, N);

    cudaLaunchAttribute pdl[1];
    pdl[0].id = cudaLaunchAttributeProgrammaticStreamSerialization;
    pdl[0].val.programmaticStreamSerializationAllowed = 1;

    {
        cudaLaunchConfig_t cfg = {};
        cfg.gridDim  = dim3((unsigned)((E * 8 + 255) / 256));
        cfg.blockDim = dim3(256);
        cfg.attrs = pdl;
        cfg.numAttrs = 1;
        cudaLaunchKernelEx(&cfg, edge_kernel, e, src, dst, E);
    }
    {
        cudaLaunchConfig_t cfg = {};
        cfg.gridDim  = dim3(148);
        cfg.blockDim = dim3(256);
        cfg.attrs = pdl;
        cfg.numAttrs = 1;
        cudaLaunchKernelEx(&cfg, node_post, N);
    }
    {
        cudaLaunchConfig_t cfg = {};
        cfg.gridDim  = dim3(1);
        cfg.blockDim = dim3(32);
        cfg.attrs = pdl;
        cfg.numAttrs = 1;
        cudaLaunchKernelEx(&cfg, finalize, gamma, beta, mmean, mvar, Wd, bd,
                           (float*)d_out);
    }
}